// round 1
// baseline (speedup 1.0000x reference)
#include <cuda_runtime.h>
#include <math.h>

// Problem constants
#define N_TOK 4096   // B*S
#define DIM   2048   // D
#define FF    1024   // F
#define NE    16     // routed experts
#define NSH   2      // shared experts
#define CAP   4096   // worst-case tokens per expert
#define TOPK  2

// ---------------- device scratch (no allocations allowed) ----------------
__device__ int   g_cnt[NE];
__device__ int   g_list[NE * CAP];
__device__ float g_wt[NE * CAP];
// Routed phase: g_h[e][m][f] = [(e*CAP+m)*FF + f]  (256 MB)
// Shared phase: g_h[m][s*FF+f] = [m*(NSH*FF) + s*FF + f]  (32 MB, reused region)
__device__ float g_h[(size_t)NE * CAP * FF];

__device__ __forceinline__ float gelu_exact(float v) {
    return 0.5f * v * (1.0f + erff(v * 0.70710678118654752440f));
}

// ---------------- kernel: zero the per-expert counters ----------------
__global__ void zero_cnt_kernel() {
    if (threadIdx.x < NE) g_cnt[threadIdx.x] = 0;
}

// ---------------- kernel: router (sigmoid affinity, top-2, renorm) ----------------
__global__ void router_kernel(const float* __restrict__ x,
                              const float* __restrict__ wa) {
    int warp_id = (blockIdx.x * blockDim.x + threadIdx.x) >> 5;
    int lane = threadIdx.x & 31;
    if (warp_id >= N_TOK) return;
    int t = warp_id;

    float acc[NE];
#pragma unroll
    for (int e = 0; e < NE; e++) acc[e] = 0.0f;

    const float* xr = x + (size_t)t * DIM;
    for (int d = lane; d < DIM; d += 32) {
        float xv = xr[d];
        const float* war = wa + (size_t)d * NE;
#pragma unroll
        for (int e = 0; e < NE; e++) acc[e] += xv * war[e];
    }
#pragma unroll
    for (int e = 0; e < NE; e++) {
#pragma unroll
        for (int o = 16; o > 0; o >>= 1)
            acc[e] += __shfl_xor_sync(0xffffffffu, acc[e], o);
    }

    if (lane == 0) {
        float aff[NE];
#pragma unroll
        for (int e = 0; e < NE; e++) aff[e] = 1.0f / (1.0f + expf(-acc[e]));
        // top-2 (strict > matches jax top_k tie-breaking: lower index first)
        int e1 = 0; float p1 = aff[0];
#pragma unroll
        for (int e = 1; e < NE; e++) if (aff[e] > p1) { p1 = aff[e]; e1 = e; }
        int e2 = (e1 == 0) ? 1 : 0; float p2 = aff[e2];
#pragma unroll
        for (int e = 0; e < NE; e++) {
            if (e != e1 && aff[e] > p2) { p2 = aff[e]; e2 = e; }
        }
        float inv = 1.0f / (p1 + p2);
        int pos1 = atomicAdd(&g_cnt[e1], 1);
        g_list[e1 * CAP + pos1] = t;
        g_wt[e1 * CAP + pos1] = p1 * inv;
        int pos2 = atomicAdd(&g_cnt[e2], 1);
        g_list[e2 * CAP + pos2] = t;
        g_wt[e2 * CAP + pos2] = p2 * inv;
    }
}

// ---------------- kernel: fused up-projection (gate + w1 + GELU-gate) ----------------
// C1 = A*G + bg ; C2 = A*W1 + b1 ; h = gelu(C1) * C2
// A rows gathered via g_list when ROUTED, identity when shared.
template <bool ROUTED>
__global__ void __launch_bounds__(256) ffn_up_kernel(
    const float* __restrict__ x,
    const float* __restrict__ Wg,   // [E][DIM][FF]
    const float* __restrict__ W1,   // [E][DIM][FF]
    const float* __restrict__ bg,   // [E][FF]
    const float* __restrict__ b1)   // [E][FF]
{
    const int e = blockIdx.z;
    const int rows = ROUTED ? g_cnt[e] : N_TOK;
    const int m0 = blockIdx.x * 64;
    if (m0 >= rows) return;
    const int f0 = blockIdx.y * 64;

    __shared__ float As[16][68];
    __shared__ float Bg[16][64];
    __shared__ float Bw[16][64];
    __shared__ int rowIdx[64];

    const int tid = threadIdx.x;
    if (tid < 64) {
        int m = m0 + tid;
        int r;
        if (ROUTED) r = (m < rows) ? g_list[e * CAP + m] : g_list[e * CAP];
        else        r = m;
        rowIdx[tid] = r;
    }
    __syncthreads();

    const int tx = tid & 15, ty = tid >> 4;
    float accG[4][4], accW[4][4];
#pragma unroll
    for (int i = 0; i < 4; i++)
#pragma unroll
        for (int j = 0; j < 4; j++) { accG[i][j] = 0.0f; accW[i][j] = 0.0f; }

    const int am = tid >> 2;          // 0..63 (m within tile)
    const int ak = (tid & 3) * 4;     // k offset 0,4,8,12
    const int bk = tid >> 4;          // 0..15
    const int bf = (tid & 15) * 4;    // 0..60

    const float* WgBase = Wg + (size_t)e * DIM * FF + f0;
    const float* W1Base = W1 + (size_t)e * DIM * FF + f0;
    const size_t arow = (size_t)rowIdx[am] * DIM;

    for (int k0 = 0; k0 < DIM; k0 += 16) {
        float4 av = *reinterpret_cast<const float4*>(x + arow + k0 + ak);
        float4 gv = *reinterpret_cast<const float4*>(WgBase + (size_t)(k0 + bk) * FF + bf);
        float4 wv = *reinterpret_cast<const float4*>(W1Base + (size_t)(k0 + bk) * FF + bf);
        __syncthreads();
        As[ak + 0][am] = av.x; As[ak + 1][am] = av.y;
        As[ak + 2][am] = av.z; As[ak + 3][am] = av.w;
        *reinterpret_cast<float4*>(&Bg[bk][bf]) = gv;
        *reinterpret_cast<float4*>(&Bw[bk][bf]) = wv;
        __syncthreads();
#pragma unroll
        for (int k = 0; k < 16; k++) {
            float a[4];
#pragma unroll
            for (int r = 0; r < 4; r++) a[r] = As[k][ty * 4 + r];
            float bgv[4], bwv[4];
            *reinterpret_cast<float4*>(bgv) = *reinterpret_cast<const float4*>(&Bg[k][tx * 4]);
            *reinterpret_cast<float4*>(bwv) = *reinterpret_cast<const float4*>(&Bw[k][tx * 4]);
#pragma unroll
            for (int r = 0; r < 4; r++)
#pragma unroll
                for (int c = 0; c < 4; c++) {
                    accG[r][c] += a[r] * bgv[c];
                    accW[r][c] += a[r] * bwv[c];
                }
        }
    }

    // epilogue: h = gelu(A*G + bg) * (A*W1 + b1)
#pragma unroll
    for (int r = 0; r < 4; r++) {
        int m = m0 + ty * 4 + r;
        if (m < rows) {
            size_t base = ROUTED ? ((size_t)e * CAP + m) * FF
                                 : ((size_t)m * (NSH * FF) + (size_t)e * FF);
#pragma unroll
            for (int c = 0; c < 4; c++) {
                int f = f0 + tx * 4 + c;
                float v1 = accG[r][c] + bg[e * FF + f];
                float v2 = accW[r][c] + b1[e * FF + f];
                g_h[base + f] = gelu_exact(v1) * v2;
            }
        }
    }
}

// ---------------- kernel: shared down-projection ----------------
// Both shared experts fused as one [4096,2048]x[2048,2048] GEMM
// (h columns s*FF+f line up with flattened sw2 rows). Writes out = x + shared.
__global__ void __launch_bounds__(256) ffn_down_shared_kernel(
    const float* __restrict__ W2flat,  // sw2 viewed [NSH*FF][DIM]
    const float* __restrict__ sb2,     // [NSH][DIM]
    const float* __restrict__ x,
    float* __restrict__ out)
{
    const int m0 = blockIdx.x * 64;
    const int d0 = blockIdx.y * 64;

    __shared__ float As[16][68];
    __shared__ float Bs[16][64];

    const int tid = threadIdx.x;
    const int tx = tid & 15, ty = tid >> 4;
    float acc[4][4];
#pragma unroll
    for (int i = 0; i < 4; i++)
#pragma unroll
        for (int j = 0; j < 4; j++) acc[i][j] = 0.0f;

    const int am = tid >> 2;
    const int ak = (tid & 3) * 4;
    const int bk = tid >> 4;
    const int bf = (tid & 15) * 4;
    const int KD = NSH * FF;  // 2048

    for (int k0 = 0; k0 < KD; k0 += 16) {
        float4 av = *reinterpret_cast<const float4*>(&g_h[(size_t)(m0 + am) * KD + k0 + ak]);
        float4 bv = *reinterpret_cast<const float4*>(W2flat + (size_t)(k0 + bk) * DIM + d0 + bf);
        __syncthreads();
        As[ak + 0][am] = av.x; As[ak + 1][am] = av.y;
        As[ak + 2][am] = av.z; As[ak + 3][am] = av.w;
        *reinterpret_cast<float4*>(&Bs[bk][bf]) = bv;
        __syncthreads();
#pragma unroll
        for (int k = 0; k < 16; k++) {
            float a[4];
#pragma unroll
            for (int r = 0; r < 4; r++) a[r] = As[k][ty * 4 + r];
            float b[4];
            *reinterpret_cast<float4*>(b) = *reinterpret_cast<const float4*>(&Bs[k][tx * 4]);
#pragma unroll
            for (int r = 0; r < 4; r++)
#pragma unroll
                for (int c = 0; c < 4; c++) acc[r][c] += a[r] * b[c];
        }
    }

#pragma unroll
    for (int r = 0; r < 4; r++) {
        int m = m0 + ty * 4 + r;
#pragma unroll
        for (int c = 0; c < 4; c++) {
            int d = d0 + tx * 4 + c;
            size_t o = (size_t)m * DIM + d;
            out[o] = x[o] + acc[r][c] + sb2[d] + sb2[DIM + d];
        }
    }
}

// ---------------- kernel: routed down-projection + weighted scatter-add ----------------
__global__ void __launch_bounds__(256) ffn_down_routed_kernel(
    const float* __restrict__ rw2,   // [E][FF][DIM]
    const float* __restrict__ rb2,   // [E][DIM]
    float* __restrict__ out)
{
    const int e = blockIdx.z;
    const int rows = g_cnt[e];
    const int m0 = blockIdx.x * 64;
    if (m0 >= rows) return;
    const int d0 = blockIdx.y * 64;

    __shared__ float As[16][68];
    __shared__ float Bs[16][64];

    const int tid = threadIdx.x;
    const int tx = tid & 15, ty = tid >> 4;
    float acc[4][4];
#pragma unroll
    for (int i = 0; i < 4; i++)
#pragma unroll
        for (int j = 0; j < 4; j++) acc[i][j] = 0.0f;

    const int am = tid >> 2;
    const int ak = (tid & 3) * 4;
    const int bk = tid >> 4;
    const int bf = (tid & 15) * 4;

    const float* Abase = &g_h[((size_t)e * CAP + m0) * FF];
    const float* Bbase = rw2 + (size_t)e * FF * DIM + d0;

    for (int k0 = 0; k0 < FF; k0 += 16) {
        float4 av = *reinterpret_cast<const float4*>(Abase + (size_t)am * FF + k0 + ak);
        float4 bv = *reinterpret_cast<const float4*>(Bbase + (size_t)(k0 + bk) * DIM + bf);
        __syncthreads();
        As[ak + 0][am] = av.x; As[ak + 1][am] = av.y;
        As[ak + 2][am] = av.z; As[ak + 3][am] = av.w;
        *reinterpret_cast<float4*>(&Bs[bk][bf]) = bv;
        __syncthreads();
#pragma unroll
        for (int k = 0; k < 16; k++) {
            float a[4];
#pragma unroll
            for (int r = 0; r < 4; r++) a[r] = As[k][ty * 4 + r];
            float b[4];
            *reinterpret_cast<float4*>(b) = *reinterpret_cast<const float4*>(&Bs[k][tx * 4]);
#pragma unroll
            for (int r = 0; r < 4; r++)
#pragma unroll
                for (int c = 0; c < 4; c++) acc[r][c] += a[r] * b[c];
        }
    }

#pragma unroll
    for (int r = 0; r < 4; r++) {
        int m = m0 + ty * 4 + r;
        if (m < rows) {
            int t = g_list[e * CAP + m];
            float w = g_wt[e * CAP + m];
#pragma unroll
            for (int c = 0; c < 4; c++) {
                int d = d0 + tx * 4 + c;
                atomicAdd(&out[(size_t)t * DIM + d], w * (acc[r][c] + rb2[e * DIM + d]));
            }
        }
    }
}

// ---------------- launch ----------------
extern "C" void kernel_launch(void* const* d_in, const int* in_sizes, int n_in,
                              void* d_out, int out_size) {
    const float* x   = (const float*)d_in[0];
    const float* wa  = (const float*)d_in[1];
    const float* rg  = (const float*)d_in[2];
    const float* rgb = (const float*)d_in[3];
    const float* rw1 = (const float*)d_in[4];
    const float* rb1 = (const float*)d_in[5];
    const float* rw2 = (const float*)d_in[6];
    const float* rb2 = (const float*)d_in[7];
    const float* sg  = (const float*)d_in[8];
    const float* sgb = (const float*)d_in[9];
    const float* sw1 = (const float*)d_in[10];
    const float* sb1 = (const float*)d_in[11];
    const float* sw2 = (const float*)d_in[12];
    const float* sb2 = (const float*)d_in[13];
    float* out = (float*)d_out;

    zero_cnt_kernel<<<1, 32>>>();
    router_kernel<<<N_TOK / 4, 128>>>(x, wa);

    // shared experts: up (both experts via gridDim.z) then fused down (+x)
    ffn_up_kernel<false><<<dim3(N_TOK / 64, FF / 64, NSH), 256>>>(x, sg, sw1, sgb, sb1);
    ffn_down_shared_kernel<<<dim3(N_TOK / 64, DIM / 64), 256>>>(sw2, sb2, x, out);

    // routed experts: up then weighted scatter-add down
    ffn_up_kernel<true><<<dim3(CAP / 64, FF / 64, NE), 256>>>(x, rg, rw1, rgb, rb1);
    ffn_down_routed_kernel<<<dim3(CAP / 64, DIM / 64, NE), 256>>>(rw2, rb2, out);
}

// round 2
// speedup vs baseline: 1.0009x; 1.0009x over previous
#include <cuda_runtime.h>
#include <math.h>

// Problem constants
#define N_TOK 4096   // B*S
#define DIM   2048   // D
#define FF    1024   // F
#define NE    16     // routed experts
#define NSH   2      // shared experts
#define CAP   4096   // worst-case tokens per expert
#define TOPK  2

// ---------------- device scratch (no allocations allowed) ----------------
__device__ int   g_cnt[NE];
__device__ int   g_list[NE * CAP];
__device__ float g_wt[NE * CAP];
// Routed phase: g_h[e][m][f] = [(e*CAP+m)*FF + f]  (256 MB)
// Shared phase: g_h[m][s*FF+f] = [m*(NSH*FF) + s*FF + f]  (32 MB, reused region)
__device__ float g_h[(size_t)NE * CAP * FF];

__device__ __forceinline__ float gelu_exact(float v) {
    return 0.5f * v * (1.0f + erff(v * 0.70710678118654752440f));
}

// ---------------- kernel: zero the per-expert counters ----------------
__global__ void zero_cnt_kernel() {
    if (threadIdx.x < NE) g_cnt[threadIdx.x] = 0;
}

// ---------------- kernel: router (sigmoid affinity, top-2, renorm) ----------------
__global__ void router_kernel(const float* __restrict__ x,
                              const float* __restrict__ wa) {
    int warp_id = (blockIdx.x * blockDim.x + threadIdx.x) >> 5;
    int lane = threadIdx.x & 31;
    if (warp_id >= N_TOK) return;
    int t = warp_id;

    float acc[NE];
#pragma unroll
    for (int e = 0; e < NE; e++) acc[e] = 0.0f;

    const float* xr = x + (size_t)t * DIM;
    for (int d = lane; d < DIM; d += 32) {
        float xv = xr[d];
        const float* war = wa + (size_t)d * NE;
#pragma unroll
        for (int e = 0; e < NE; e++) acc[e] += xv * war[e];
    }
#pragma unroll
    for (int e = 0; e < NE; e++) {
#pragma unroll
        for (int o = 16; o > 0; o >>= 1)
            acc[e] += __shfl_xor_sync(0xffffffffu, acc[e], o);
    }

    if (lane == 0) {
        float aff[NE];
#pragma unroll
        for (int e = 0; e < NE; e++) aff[e] = 1.0f / (1.0f + expf(-acc[e]));
        // top-2 (strict > matches jax top_k tie-breaking: lower index first)
        int e1 = 0; float p1 = aff[0];
#pragma unroll
        for (int e = 1; e < NE; e++) if (aff[e] > p1) { p1 = aff[e]; e1 = e; }
        int e2 = (e1 == 0) ? 1 : 0; float p2 = aff[e2];
#pragma unroll
        for (int e = 0; e < NE; e++) {
            if (e != e1 && aff[e] > p2) { p2 = aff[e]; e2 = e; }
        }
        float inv = 1.0f / (p1 + p2);
        int pos1 = atomicAdd(&g_cnt[e1], 1);
        g_list[e1 * CAP + pos1] = t;
        g_wt[e1 * CAP + pos1] = p1 * inv;
        int pos2 = atomicAdd(&g_cnt[e2], 1);
        g_list[e2 * CAP + pos2] = t;
        g_wt[e2 * CAP + pos2] = p2 * inv;
    }
}

// ---------------- kernel: fused up-projection (gate + w1 + GELU-gate) ----------------
// C1 = A*G + bg ; C2 = A*W1 + b1 ; h = gelu(C1) * C2
// A rows gathered via g_list when ROUTED, identity when shared.
template <bool ROUTED>
__global__ void __launch_bounds__(256) ffn_up_kernel(
    const float* __restrict__ x,
    const float* __restrict__ Wg,   // [E][DIM][FF]
    const float* __restrict__ W1,   // [E][DIM][FF]
    const float* __restrict__ bg,   // [E][FF]
    const float* __restrict__ b1)   // [E][FF]
{
    const int e = blockIdx.z;
    const int rows = ROUTED ? g_cnt[e] : N_TOK;
    const int m0 = blockIdx.x * 64;
    if (m0 >= rows) return;
    const int f0 = blockIdx.y * 64;

    __shared__ float As[16][68];
    __shared__ float Bg[16][64];
    __shared__ float Bw[16][64];
    __shared__ int rowIdx[64];

    const int tid = threadIdx.x;
    if (tid < 64) {
        int m = m0 + tid;
        int r;
        if (ROUTED) r = (m < rows) ? g_list[e * CAP + m] : g_list[e * CAP];
        else        r = m;
        rowIdx[tid] = r;
    }
    __syncthreads();

    const int tx = tid & 15, ty = tid >> 4;
    float accG[4][4], accW[4][4];
#pragma unroll
    for (int i = 0; i < 4; i++)
#pragma unroll
        for (int j = 0; j < 4; j++) { accG[i][j] = 0.0f; accW[i][j] = 0.0f; }

    const int am = tid >> 2;          // 0..63 (m within tile)
    const int ak = (tid & 3) * 4;     // k offset 0,4,8,12
    const int bk = tid >> 4;          // 0..15
    const int bf = (tid & 15) * 4;    // 0..60

    const float* WgBase = Wg + (size_t)e * DIM * FF + f0;
    const float* W1Base = W1 + (size_t)e * DIM * FF + f0;
    const size_t arow = (size_t)rowIdx[am] * DIM;

    for (int k0 = 0; k0 < DIM; k0 += 16) {
        float4 av = *reinterpret_cast<const float4*>(x + arow + k0 + ak);
        float4 gv = *reinterpret_cast<const float4*>(WgBase + (size_t)(k0 + bk) * FF + bf);
        float4 wv = *reinterpret_cast<const float4*>(W1Base + (size_t)(k0 + bk) * FF + bf);
        __syncthreads();
        As[ak + 0][am] = av.x; As[ak + 1][am] = av.y;
        As[ak + 2][am] = av.z; As[ak + 3][am] = av.w;
        *reinterpret_cast<float4*>(&Bg[bk][bf]) = gv;
        *reinterpret_cast<float4*>(&Bw[bk][bf]) = wv;
        __syncthreads();
#pragma unroll
        for (int k = 0; k < 16; k++) {
            float a[4];
#pragma unroll
            for (int r = 0; r < 4; r++) a[r] = As[k][ty * 4 + r];
            float bgv[4], bwv[4];
            *reinterpret_cast<float4*>(bgv) = *reinterpret_cast<const float4*>(&Bg[k][tx * 4]);
            *reinterpret_cast<float4*>(bwv) = *reinterpret_cast<const float4*>(&Bw[k][tx * 4]);
#pragma unroll
            for (int r = 0; r < 4; r++)
#pragma unroll
                for (int c = 0; c < 4; c++) {
                    accG[r][c] += a[r] * bgv[c];
                    accW[r][c] += a[r] * bwv[c];
                }
        }
    }

    // epilogue: h = gelu(A*G + bg) * (A*W1 + b1)
#pragma unroll
    for (int r = 0; r < 4; r++) {
        int m = m0 + ty * 4 + r;
        if (m < rows) {
            size_t base = ROUTED ? ((size_t)e * CAP + m) * FF
                                 : ((size_t)m * (NSH * FF) + (size_t)e * FF);
#pragma unroll
            for (int c = 0; c < 4; c++) {
                int f = f0 + tx * 4 + c;
                float v1 = accG[r][c] + bg[e * FF + f];
                float v2 = accW[r][c] + b1[e * FF + f];
                g_h[base + f] = gelu_exact(v1) * v2;
            }
        }
    }
}

// ---------------- kernel: shared down-projection ----------------
// Both shared experts fused as one [4096,2048]x[2048,2048] GEMM
// (h columns s*FF+f line up with flattened sw2 rows). Writes out = x + shared.
__global__ void __launch_bounds__(256) ffn_down_shared_kernel(
    const float* __restrict__ W2flat,  // sw2 viewed [NSH*FF][DIM]
    const float* __restrict__ sb2,     // [NSH][DIM]
    const float* __restrict__ x,
    float* __restrict__ out)
{
    const int m0 = blockIdx.x * 64;
    const int d0 = blockIdx.y * 64;

    __shared__ float As[16][68];
    __shared__ float Bs[16][64];

    const int tid = threadIdx.x;
    const int tx = tid & 15, ty = tid >> 4;
    float acc[4][4];
#pragma unroll
    for (int i = 0; i < 4; i++)
#pragma unroll
        for (int j = 0; j < 4; j++) acc[i][j] = 0.0f;

    const int am = tid >> 2;
    const int ak = (tid & 3) * 4;
    const int bk = tid >> 4;
    const int bf = (tid & 15) * 4;
    const int KD = NSH * FF;  // 2048

    for (int k0 = 0; k0 < KD; k0 += 16) {
        float4 av = *reinterpret_cast<const float4*>(&g_h[(size_t)(m0 + am) * KD + k0 + ak]);
        float4 bv = *reinterpret_cast<const float4*>(W2flat + (size_t)(k0 + bk) * DIM + d0 + bf);
        __syncthreads();
        As[ak + 0][am] = av.x; As[ak + 1][am] = av.y;
        As[ak + 2][am] = av.z; As[ak + 3][am] = av.w;
        *reinterpret_cast<float4*>(&Bs[bk][bf]) = bv;
        __syncthreads();
#pragma unroll
        for (int k = 0; k < 16; k++) {
            float a[4];
#pragma unroll
            for (int r = 0; r < 4; r++) a[r] = As[k][ty * 4 + r];
            float b[4];
            *reinterpret_cast<float4*>(b) = *reinterpret_cast<const float4*>(&Bs[k][tx * 4]);
#pragma unroll
            for (int r = 0; r < 4; r++)
#pragma unroll
                for (int c = 0; c < 4; c++) acc[r][c] += a[r] * b[c];
        }
    }

#pragma unroll
    for (int r = 0; r < 4; r++) {
        int m = m0 + ty * 4 + r;
#pragma unroll
        for (int c = 0; c < 4; c++) {
            int d = d0 + tx * 4 + c;
            size_t o = (size_t)m * DIM + d;
            out[o] = x[o] + acc[r][c] + sb2[d] + sb2[DIM + d];
        }
    }
}

// ---------------- kernel: routed down-projection + weighted scatter-add ----------------
__global__ void __launch_bounds__(256) ffn_down_routed_kernel(
    const float* __restrict__ rw2,   // [E][FF][DIM]
    const float* __restrict__ rb2,   // [E][DIM]
    float* __restrict__ out)
{
    const int e = blockIdx.z;
    const int rows = g_cnt[e];
    const int m0 = blockIdx.x * 64;
    if (m0 >= rows) return;
    const int d0 = blockIdx.y * 64;

    __shared__ float As[16][68];
    __shared__ float Bs[16][64];

    const int tid = threadIdx.x;
    const int tx = tid & 15, ty = tid >> 4;
    float acc[4][4];
#pragma unroll
    for (int i = 0; i < 4; i++)
#pragma unroll
        for (int j = 0; j < 4; j++) acc[i][j] = 0.0f;

    const int am = tid >> 2;
    const int ak = (tid & 3) * 4;
    const int bk = tid >> 4;
    const int bf = (tid & 15) * 4;

    const float* Abase = &g_h[((size_t)e * CAP + m0) * FF];
    const float* Bbase = rw2 + (size_t)e * FF * DIM + d0;

    for (int k0 = 0; k0 < FF; k0 += 16) {
        float4 av = *reinterpret_cast<const float4*>(Abase + (size_t)am * FF + k0 + ak);
        float4 bv = *reinterpret_cast<const float4*>(Bbase + (size_t)(k0 + bk) * DIM + bf);
        __syncthreads();
        As[ak + 0][am] = av.x; As[ak + 1][am] = av.y;
        As[ak + 2][am] = av.z; As[ak + 3][am] = av.w;
        *reinterpret_cast<float4*>(&Bs[bk][bf]) = bv;
        __syncthreads();
#pragma unroll
        for (int k = 0; k < 16; k++) {
            float a[4];
#pragma unroll
            for (int r = 0; r < 4; r++) a[r] = As[k][ty * 4 + r];
            float b[4];
            *reinterpret_cast<float4*>(b) = *reinterpret_cast<const float4*>(&Bs[k][tx * 4]);
#pragma unroll
            for (int r = 0; r < 4; r++)
#pragma unroll
                for (int c = 0; c < 4; c++) acc[r][c] += a[r] * b[c];
        }
    }

#pragma unroll
    for (int r = 0; r < 4; r++) {
        int m = m0 + ty * 4 + r;
        if (m < rows) {
            int t = g_list[e * CAP + m];
            float w = g_wt[e * CAP + m];
#pragma unroll
            for (int c = 0; c < 4; c++) {
                int d = d0 + tx * 4 + c;
                atomicAdd(&out[(size_t)t * DIM + d], w * (acc[r][c] + rb2[e * DIM + d]));
            }
        }
    }
}

// ---------------- launch ----------------
extern "C" void kernel_launch(void* const* d_in, const int* in_sizes, int n_in,
                              void* d_out, int out_size) {
    const float* x   = (const float*)d_in[0];
    const float* wa  = (const float*)d_in[1];
    const float* rg  = (const float*)d_in[2];
    const float* rgb = (const float*)d_in[3];
    const float* rw1 = (const float*)d_in[4];
    const float* rb1 = (const float*)d_in[5];
    const float* rw2 = (const float*)d_in[6];
    const float* rb2 = (const float*)d_in[7];
    const float* sg  = (const float*)d_in[8];
    const float* sgb = (const float*)d_in[9];
    const float* sw1 = (const float*)d_in[10];
    const float* sb1 = (const float*)d_in[11];
    const float* sw2 = (const float*)d_in[12];
    const float* sb2 = (const float*)d_in[13];
    float* out = (float*)d_out;

    zero_cnt_kernel<<<1, 32>>>();
    router_kernel<<<N_TOK / 4, 128>>>(x, wa);

    // shared experts: up (both experts via gridDim.z) then fused down (+x)
    ffn_up_kernel<false><<<dim3(N_TOK / 64, FF / 64, NSH), 256>>>(x, sg, sw1, sgb, sb1);
    ffn_down_shared_kernel<<<dim3(N_TOK / 64, DIM / 64), 256>>>(sw2, sb2, x, out);

    // routed experts: up then weighted scatter-add down
    ffn_up_kernel<true><<<dim3(CAP / 64, FF / 64, NE), 256>>>(x, rg, rw1, rgb, rb1);
    ffn_down_routed_kernel<<<dim3(CAP / 64, DIM / 64, NE), 256>>>(rw2, rb2, out);
}

// round 4
// speedup vs baseline: 2.7395x; 2.7372x over previous
#include <cuda_runtime.h>
#include <cstdint>
#include <math.h>

#define N_TOK 4096
#define DIM   2048
#define FF    1024
#define NE    16
#define CAP   4096

__device__ int   g_cnt[NE];
__device__ int   g_list[NE * CAP];
__device__ float g_wt[NE * CAP];
__device__ float g_h[(size_t)NE * CAP * FF];

// ---------- helpers ----------
__device__ __forceinline__ uint32_t smem_u32(const void* p) {
    uint32_t a;
    asm("{ .reg .u64 t; cvta.to.shared.u64 t, %1; cvt.u32.u64 %0, t; }" : "=r"(a) : "l"(p));
    return a;
}
__device__ __forceinline__ uint32_t tf32c(float v) {
    uint32_t r;
    asm("cvt.rna.tf32.f32 %0, %1;" : "=r"(r) : "f"(v));
    return r;
}
__device__ __forceinline__ void sts4(uint32_t a, uint32_t x, uint32_t y, uint32_t z, uint32_t w) {
    asm volatile("st.shared.v4.b32 [%0],{%1,%2,%3,%4};" :: "r"(a), "r"(x), "r"(y), "r"(z), "r"(w));
}
__device__ __forceinline__ void ldm4(uint32_t* r, uint32_t a) {
    asm volatile("ldmatrix.sync.aligned.m8n8.x4.shared.b16 {%0,%1,%2,%3}, [%4];"
                 : "=r"(r[0]), "=r"(r[1]), "=r"(r[2]), "=r"(r[3]) : "r"(a));
}
__device__ __forceinline__ void mma8(float* d, const uint32_t* a, uint32_t b0, uint32_t b1) {
    asm volatile("mma.sync.aligned.m16n8k8.row.col.f32.tf32.tf32.f32 "
                 "{%0,%1,%2,%3},{%4,%5,%6,%7},{%8,%9},{%0,%1,%2,%3};"
                 : "+f"(d[0]), "+f"(d[1]), "+f"(d[2]), "+f"(d[3])
                 : "r"(a[0]), "r"(a[1]), "r"(a[2]), "r"(a[3]), "r"(b0), "r"(b1));
}
__device__ __forceinline__ float gelu_exact(float v) {
    return 0.5f * v * (1.0f + erff(v * 0.70710678118654752440f));
}

// ---------- router ----------
__global__ void zero_cnt_kernel() { if (threadIdx.x < NE) g_cnt[threadIdx.x] = 0; }

__global__ void router_kernel(const float* __restrict__ x, const float* __restrict__ wa) {
    int t = (blockIdx.x * blockDim.x + threadIdx.x) >> 5;
    int lane = threadIdx.x & 31;
    if (t >= N_TOK) return;
    float acc[NE];
#pragma unroll
    for (int e = 0; e < NE; e++) acc[e] = 0.0f;
    const float* xr = x + (size_t)t * DIM;
    for (int d = lane; d < DIM; d += 32) {
        float xv = xr[d];
#pragma unroll
        for (int e = 0; e < NE; e++) acc[e] += xv * wa[(size_t)d * NE + e];
    }
#pragma unroll
    for (int e = 0; e < NE; e++)
#pragma unroll
        for (int o = 16; o > 0; o >>= 1) acc[e] += __shfl_xor_sync(0xffffffffu, acc[e], o);
    if (lane == 0) {
        float aff[NE];
#pragma unroll
        for (int e = 0; e < NE; e++) aff[e] = 1.0f / (1.0f + expf(-acc[e]));
        int e1 = 0; float p1 = aff[0];
#pragma unroll
        for (int e = 1; e < NE; e++) if (aff[e] > p1) { p1 = aff[e]; e1 = e; }
        int e2 = (e1 == 0) ? 1 : 0; float p2 = aff[e2];
#pragma unroll
        for (int e = 0; e < NE; e++) if (e != e1 && aff[e] > p2) { p2 = aff[e]; e2 = e; }
        float inv = 1.0f / (p1 + p2);
        int q1 = atomicAdd(&g_cnt[e1], 1);
        g_list[e1 * CAP + q1] = t; g_wt[e1 * CAP + q1] = p1 * inv;
        int q2 = atomicAdd(&g_cnt[e2], 1);
        g_list[e2 * CAP + q2] = t; g_wt[e2 * CAP + q2] = p2 * inv;
    }
}

// ---------- unified warp-MMA GEMM ----------
// modes: 0 up-shared, 1 up-routed, 2 down-shared, 3 down-routed
template <int MODE>
__global__ void __launch_bounds__(256, 2) mma_kernel(
    const float* __restrict__ Asrc, const float* __restrict__ W0p,
    const float* __restrict__ W1p, const float* __restrict__ bias0,
    const float* __restrict__ bias1, const float* __restrict__ xres,
    float* __restrict__ outp)
{
    constexpr bool UP = (MODE <= 1);
    constexpr int KT  = (MODE == 3) ? FF : DIM;
    constexpr int LDB = UP ? FF : DIM;
    constexpr int LDA = (MODE == 3) ? FF : DIM;
    constexpr int NCH = KT / 16;
    constexpr int STAGE = 32768;   // 16K A + 16K B per stage
    constexpr int NMI = UP ? 2 : 4;
    constexpr int NBG = UP ? 4 : 2;
    constexpr int NNT = UP ? 8 : 4;

    const int e = blockIdx.z;
    const int rows = (MODE == 1 || MODE == 3) ? g_cnt[e] : N_TOK;
    const int m0 = blockIdx.x * 128;
    if (m0 >= rows) return;
    const int n0 = blockIdx.y * (UP ? 64 : 128);

    extern __shared__ char dynsm[];
    __shared__ int s_row[128];
    const int tid = threadIdx.x, wid = tid >> 5, lane = tid & 31;
    const uint32_t sbase = smem_u32(dynsm);

    if (tid < 128) {
        int mm = m0 + tid;
        s_row[tid] = (MODE == 1) ? g_list[e * CAP + (mm < rows ? mm : m0)] : mm;
    }
    __syncthreads();

    // ---- loader setup ----
    const float* Ab = UP ? Asrc : (MODE == 2 ? g_h : g_h + (size_t)e * CAP * FF);
    const float* aP = Ab + (size_t)s_row[tid >> 1] * LDA + (tid & 1) * 4;
    const int bn = tid & 127;
    const int kb = (tid >> 7) * 8;
    const float* bcol;
    if (UP) {
        const float* WgB = W0p + (size_t)e * DIM * FF;
        const float* W1B = W1p + (size_t)e * DIM * FF;
        bcol = (bn < 64) ? (WgB + n0 + bn) : (W1B + n0 + bn - 64);
    } else {
        bcol = W0p + ((MODE == 3) ? (size_t)e * FF * DIM : (size_t)0) + n0 + bn;
    }
    bcol += (size_t)kb * LDB;
    const uint32_t a_sts = sbase + (uint32_t)(tid >> 1) * 128;
    const uint32_t xra = (uint32_t)(((tid >> 1) & 7) << 4);
    const uint32_t a_c0 = ((uint32_t)(tid & 1) * 16) ^ xra;
    const uint32_t a_c1 = (((uint32_t)(tid & 1) + 2) * 16) ^ xra;
    const uint32_t b_sts = sbase + 16384 + (uint32_t)bn * 128;
    const uint32_t xrb = (uint32_t)((bn & 7) << 4);
    const uint32_t b_c0 = ((uint32_t)kb * 4) ^ xrb;
    const uint32_t b_c1 = ((uint32_t)(kb + 4) * 4) ^ xrb;

    float4 av0, av1;
    float bv[8];
    auto ldregs = [&](int k0) {
        av0 = *(const float4*)(aP + k0);
        av1 = *(const float4*)(aP + k0 + 8);
        const float* bp = bcol + (size_t)k0 * LDB;
#pragma unroll
        for (int q = 0; q < 8; q++) bv[q] = bp[(size_t)q * LDB];
    };
    auto stregs = [&](uint32_t off) {
        sts4(a_sts + off + a_c0, tf32c(av0.x), tf32c(av0.y), tf32c(av0.z), tf32c(av0.w));
        sts4(a_sts + off + a_c1, tf32c(av1.x), tf32c(av1.y), tf32c(av1.z), tf32c(av1.w));
        sts4(b_sts + off + b_c0, tf32c(bv[0]), tf32c(bv[1]), tf32c(bv[2]), tf32c(bv[3]));
        sts4(b_sts + off + b_c1, tf32c(bv[4]), tf32c(bv[5]), tf32c(bv[6]), tf32c(bv[7]));
    };

    // ---- warp fragment addressing ----
    const int wm = UP ? (wid >> 1) : (wid & 1);
    const int wn = UP ? (wid & 1) : (wid >> 1);
    const int m_off = wm * (UP ? 32 : 64);
    const int lr = (lane & 7) | (((lane >> 3) & 1) << 3);
    const uint32_t xr = (uint32_t)((lane & 7) << 4);
    const uint32_t hi16 = (uint32_t)(((lane >> 4) & 1) * 16);
    uint32_t aoff[NMI], boff[NBG];
#pragma unroll
    for (int mi = 0; mi < NMI; mi++) aoff[mi] = (uint32_t)(m_off + mi * 16 + lr) * 128;
#pragma unroll
    for (int g = 0; g < NBG; g++) {
        int r0 = UP ? ((g >= 2 ? 64 : 0) + wn * 32 + (g & 1) * 16) : (wn * 32 + g * 16);
        boff[g] = 16384u + (uint32_t)(r0 + lr) * 128;
    }

    float acc[NMI * NNT][4];
#pragma unroll
    for (int i = 0; i < NMI * NNT; i++)
#pragma unroll
        for (int j = 0; j < 4; j++) acc[i][j] = 0.0f;

    // ---- pipelined main loop (1 barrier per chunk) ----
    ldregs(0);
    stregs(0);
    __syncthreads();
    for (int it = 0; it < NCH; it++) {
        if (it + 1 < NCH) ldregs((it + 1) * 16);
        const uint32_t abase = sbase + (uint32_t)(it & 1) * STAGE - sbase;  // stage offset
        const uint32_t soff = (uint32_t)(it & 1) * STAGE;
#pragma unroll
        for (int ks = 0; ks < 2; ks++) {
            const uint32_t inn = ((uint32_t)(ks * 32) + hi16) ^ xr;
            uint32_t af[NMI][4];
#pragma unroll
            for (int mi = 0; mi < NMI; mi++) ldm4(af[mi], sbase + soff + aoff[mi] + inn);
            uint32_t bf[NBG][4];
#pragma unroll
            for (int g = 0; g < NBG; g++) ldm4(bf[g], sbase + soff + boff[g] + inn);
#pragma unroll
            for (int mi = 0; mi < NMI; mi++)
#pragma unroll
                for (int nt = 0; nt < NNT; nt++)
                    mma8(acc[mi * NNT + nt], af[mi], bf[nt >> 1][nt & 1], bf[nt >> 1][(nt & 1) + 2]);
        }
        (void)abase;
        if (it + 1 < NCH) {
            stregs((uint32_t)((it + 1) & 1) * STAGE);
            __syncthreads();
        }
    }

    // ---- epilogue ----
    const int rbase = lane >> 2;
    const int cbase = (lane & 3) * 2;
    if (UP) {
#pragma unroll
        for (int mi = 0; mi < NMI; mi++) {
#pragma unroll
            for (int h = 0; h < 2; h++) {
                const int m = m0 + m_off + mi * 16 + rbase + h * 8;
                if (m >= rows) continue;
#pragma unroll
                for (int nt = 0; nt < 4; nt++) {
                    const int f = n0 + wn * 32 + nt * 8 + cbase;
                    const float* bg = bias0 + (size_t)e * FF + f;
                    const float* b1 = bias1 + (size_t)e * FF + f;
                    float c1a = acc[mi * NNT + nt][h * 2 + 0] + bg[0];
                    float c1b = acc[mi * NNT + nt][h * 2 + 1] + bg[1];
                    float c2a = acc[mi * NNT + nt + 4][h * 2 + 0] + b1[0];
                    float c2b = acc[mi * NNT + nt + 4][h * 2 + 1] + b1[1];
                    float2 hv = make_float2(gelu_exact(c1a) * c2a, gelu_exact(c1b) * c2b);
                    float* dst = (MODE == 0)
                        ? (g_h + (size_t)m * (2 * FF) + (size_t)e * FF + f)
                        : (g_h + ((size_t)e * CAP + m) * FF + f);
                    *(float2*)dst = hv;
                }
            }
        }
    } else {
#pragma unroll
        for (int mi = 0; mi < NMI; mi++) {
#pragma unroll
            for (int h = 0; h < 2; h++) {
                const int m = m0 + m_off + mi * 16 + rbase + h * 8;
                if (m >= rows) continue;
                int tok = 0; float w = 0.0f;
                if (MODE == 3) { tok = g_list[e * CAP + m]; w = g_wt[e * CAP + m]; }
#pragma unroll
                for (int nt = 0; nt < 4; nt++) {
                    const int d = n0 + wn * 32 + nt * 8 + cbase;
                    float v0 = acc[mi * NNT + nt][h * 2 + 0];
                    float v1 = acc[mi * NNT + nt][h * 2 + 1];
                    if (MODE == 2) {
                        size_t o = (size_t)m * DIM + d;
                        float2 xv = *(const float2*)(xres + o);
                        float2 ov = make_float2(
                            xv.x + v0 + bias0[d] + bias0[DIM + d],
                            xv.y + v1 + bias0[d + 1] + bias0[DIM + d + 1]);
                        *(float2*)(outp + o) = ov;
                    } else {
                        float* dst = outp + (size_t)tok * DIM + d;
                        atomicAdd(dst + 0, w * (v0 + bias0[(size_t)e * DIM + d]));
                        atomicAdd(dst + 1, w * (v1 + bias0[(size_t)e * DIM + d + 1]));
                    }
                }
            }
        }
    }
}

// ---------- launch ----------
extern "C" void kernel_launch(void* const* d_in, const int* in_sizes, int n_in,
                              void* d_out, int out_size) {
    const float* x   = (const float*)d_in[0];
    const float* wa  = (const float*)d_in[1];
    const float* rg  = (const float*)d_in[2];
    const float* rgb = (const float*)d_in[3];
    const float* rw1 = (const float*)d_in[4];
    const float* rb1 = (const float*)d_in[5];
    const float* rw2 = (const float*)d_in[6];
    const float* rb2 = (const float*)d_in[7];
    const float* sg  = (const float*)d_in[8];
    const float* sgb = (const float*)d_in[9];
    const float* sw1 = (const float*)d_in[10];
    const float* sb1 = (const float*)d_in[11];
    const float* sw2 = (const float*)d_in[12];
    const float* sb2 = (const float*)d_in[13];
    float* out = (float*)d_out;

    const int smem = 2 * 32768;
    cudaFuncSetAttribute(mma_kernel<0>, cudaFuncAttributeMaxDynamicSharedMemorySize, smem);
    cudaFuncSetAttribute(mma_kernel<1>, cudaFuncAttributeMaxDynamicSharedMemorySize, smem);
    cudaFuncSetAttribute(mma_kernel<2>, cudaFuncAttributeMaxDynamicSharedMemorySize, smem);
    cudaFuncSetAttribute(mma_kernel<3>, cudaFuncAttributeMaxDynamicSharedMemorySize, smem);

    zero_cnt_kernel<<<1, 32>>>();
    router_kernel<<<N_TOK / 4, 128>>>(x, wa);

    // shared: fused up (both experts), then down (+x +biases), h in g_h[m][2*FF]
    mma_kernel<0><<<dim3(N_TOK / 128, FF / 64, 2), 256, smem>>>(x, sg, sw1, sgb, sb1, nullptr, nullptr);
    mma_kernel<2><<<dim3(N_TOK / 128, DIM / 128, 1), 256, smem>>>(nullptr, sw2, nullptr, sb2, nullptr, x, out);

    // routed: up (gathered rows), then weighted scatter-add down
    mma_kernel<1><<<dim3(CAP / 128, FF / 64, NE), 256, smem>>>(x, rg, rw1, rgb, rb1, nullptr, nullptr);
    mma_kernel<3><<<dim3(CAP / 128, DIM / 128, NE), 256, smem>>>(nullptr, rw2, nullptr, rb2, nullptr, nullptr, out);
}

// round 5
// speedup vs baseline: 4.5052x; 1.6445x over previous
#include <cuda_runtime.h>
#include <cuda_fp16.h>
#include <cstdint>
#include <math.h>

#define N_TOK 4096
#define DIM   2048
#define FF    1024
#define NE    16
#define CAP   4096

// half-buffer offsets (in halves)
#define OXH  0ull
#define ORG  (8ull  << 20)
#define ORW1 (40ull << 20)
#define ORW2 (72ull << 20)
#define OSG  (104ull << 20)
#define OSW1 (108ull << 20)
#define OSW2 (112ull << 20)

__device__ int    g_cnt[NE];
__device__ int    g_list[NE * CAP];
__device__ float  g_wt[NE * CAP];
__device__ __half g_half[116ull << 20];                 // converted x + weights
__device__ __half g_hh[(size_t)NE * CAP * FF];          // fp16 hidden activations

// ---------- helpers ----------
__device__ __forceinline__ uint32_t smem_u32(const void* p) {
    uint32_t a;
    asm("{ .reg .u64 t; cvta.to.shared.u64 t, %1; cvt.u32.u64 %0, t; }" : "=r"(a) : "l"(p));
    return a;
}
__device__ __forceinline__ void cp16(uint32_t dst, const void* src) {
    asm volatile("cp.async.cg.shared.global [%0], [%1], 16;" :: "r"(dst), "l"(src));
}
__device__ __forceinline__ void ldm4(uint32_t* r, uint32_t a) {
    asm volatile("ldmatrix.sync.aligned.m8n8.x4.shared.b16 {%0,%1,%2,%3}, [%4];"
                 : "=r"(r[0]), "=r"(r[1]), "=r"(r[2]), "=r"(r[3]) : "r"(a));
}
__device__ __forceinline__ void ldm4t(uint32_t* r, uint32_t a) {
    asm volatile("ldmatrix.sync.aligned.m8n8.x4.trans.shared.b16 {%0,%1,%2,%3}, [%4];"
                 : "=r"(r[0]), "=r"(r[1]), "=r"(r[2]), "=r"(r[3]) : "r"(a));
}
__device__ __forceinline__ void mma16(float* d, const uint32_t* a, uint32_t b0, uint32_t b1) {
    asm volatile("mma.sync.aligned.m16n8k16.row.col.f32.f16.f16.f32 "
                 "{%0,%1,%2,%3},{%4,%5,%6,%7},{%8,%9},{%0,%1,%2,%3};"
                 : "+f"(d[0]), "+f"(d[1]), "+f"(d[2]), "+f"(d[3])
                 : "r"(a[0]), "r"(a[1]), "r"(a[2]), "r"(a[3]), "r"(b0), "r"(b1));
}
__device__ __forceinline__ float gelu_exact(float v) {
    return 0.5f * v * (1.0f + erff(v * 0.70710678118654752440f));
}

// ---------- conversion fp32 -> fp16 ----------
__global__ void cvt_kernel(const float* __restrict__ src, size_t dofs, size_t n) {
    size_t i = ((size_t)blockIdx.x * 256 + threadIdx.x) * 4;
    if (i >= n) return;
    float4 v = *(const float4*)(src + i);
    __half2* d = (__half2*)(g_half + dofs + i);
    d[0] = __floats2half2_rn(v.x, v.y);
    d[1] = __floats2half2_rn(v.z, v.w);
}

// ---------- router ----------
__global__ void zero_cnt_kernel() { if (threadIdx.x < NE) g_cnt[threadIdx.x] = 0; }

__global__ void router_kernel(const float* __restrict__ x, const float* __restrict__ wa) {
    int t = (blockIdx.x * blockDim.x + threadIdx.x) >> 5;
    int lane = threadIdx.x & 31;
    if (t >= N_TOK) return;
    float acc[NE];
#pragma unroll
    for (int e = 0; e < NE; e++) acc[e] = 0.0f;
    const float* xr = x + (size_t)t * DIM;
    for (int d = lane; d < DIM; d += 32) {
        float xv = xr[d];
#pragma unroll
        for (int e = 0; e < NE; e++) acc[e] += xv * wa[(size_t)d * NE + e];
    }
#pragma unroll
    for (int e = 0; e < NE; e++)
#pragma unroll
        for (int o = 16; o > 0; o >>= 1) acc[e] += __shfl_xor_sync(0xffffffffu, acc[e], o);
    if (lane == 0) {
        float aff[NE];
#pragma unroll
        for (int e = 0; e < NE; e++) aff[e] = 1.0f / (1.0f + expf(-acc[e]));
        int e1 = 0; float p1 = aff[0];
#pragma unroll
        for (int e = 1; e < NE; e++) if (aff[e] > p1) { p1 = aff[e]; e1 = e; }
        int e2 = (e1 == 0) ? 1 : 0; float p2 = aff[e2];
#pragma unroll
        for (int e = 0; e < NE; e++) if (e != e1 && aff[e] > p2) { p2 = aff[e]; e2 = e; }
        float inv = 1.0f / (p1 + p2);
        int q1 = atomicAdd(&g_cnt[e1], 1);
        g_list[e1 * CAP + q1] = t; g_wt[e1 * CAP + q1] = p1 * inv;
        int q2 = atomicAdd(&g_cnt[e2], 1);
        g_list[e2 * CAP + q2] = t; g_wt[e2 * CAP + q2] = p2 * inv;
    }
}

// ---------- fp16 warp-MMA GEMM, cp.async 3-stage ----------
// modes: 0 up-shared, 1 up-routed, 2 down-shared, 3 down-routed
template <int MODE>
__global__ void __launch_bounds__(256, 2) mma_kernel(
    const float* __restrict__ bias0, const float* __restrict__ bias1,
    const float* __restrict__ xres, float* __restrict__ outp)
{
    constexpr bool UP = (MODE <= 1);
    constexpr int KT   = (MODE == 3) ? FF : DIM;
    constexpr int LDAh = (MODE == 3) ? FF : DIM;
    constexpr int LDBh = UP ? FF : DIM;
    constexpr int NCH  = KT / 64;
    constexpr int NMI  = UP ? 2 : 4;
    constexpr int NBG  = UP ? 4 : 2;
    constexpr int NNT  = UP ? 8 : 4;

    const int e = blockIdx.z;
    const int rows = (MODE == 1 || MODE == 3) ? g_cnt[e] : N_TOK;
    const int m0 = blockIdx.x * 128;
    if (m0 >= rows) return;
    const int n0 = blockIdx.y * (UP ? 64 : 128);

    extern __shared__ char dynsm[];
    __shared__ int s_row[128];
    const int tid = threadIdx.x, wid = tid >> 5, lane = tid & 31;
    const uint32_t sbase = smem_u32(dynsm);

    if (tid < 128) {
        int mm = m0 + tid;
        s_row[tid] = (MODE == 1) ? g_list[e * CAP + (mm < rows ? mm : m0)] : mm;
    }
    __syncthreads();

    // ---- cp.async source/dest setup ----
    const __half* Ah = UP ? (g_half + OXH)
                          : (MODE == 2 ? g_hh : g_hh + (size_t)e * CAP * FF);
    const __half* aSrc = Ah + (size_t)s_row[tid >> 1] * LDAh + (size_t)(tid & 1) * 32;
    const uint32_t a_dst = (uint32_t)((tid >> 1) * 128);
    const uint32_t a_xor = (uint32_t)(((tid >> 1) & 7) << 4);
    const uint32_t a_seg = (uint32_t)((tid & 1) * 64);

    const int krow = tid >> 2, nseg = tid & 3;
    const __half* Bh;
    if (UP) {
        const __half* G = (MODE == 0 ? g_half + OSG : g_half + ORG) + (size_t)e * DIM * FF;
        const __half* W = (MODE == 0 ? g_half + OSW1 : g_half + ORW1) + (size_t)e * DIM * FF;
        Bh = (nseg < 2 ? G : W) + n0 + (size_t)(nseg & 1) * 32;
    } else {
        Bh = (MODE == 2 ? g_half + OSW2 : g_half + ORW2 + (size_t)e * FF * DIM)
             + n0 + (size_t)nseg * 32;
    }
    const __half* bSrc = Bh + (size_t)krow * LDBh;
    const uint32_t b_dst = (uint32_t)(16384 + krow * 256);
    const uint32_t b_xor = (uint32_t)((krow & 7) << 4);
    const uint32_t b_seg = (uint32_t)(nseg * 64);

#define ISSUE(s, buf) do { \
    uint32_t sA_ = sbase + (uint32_t)(buf) * 32768u; \
    const char* as_ = (const char*)(aSrc + (size_t)(s) * 64); \
    const char* bs_ = (const char*)(bSrc + (size_t)(s) * 64 * LDBh); \
    _Pragma("unroll") \
    for (int j = 0; j < 4; j++) \
        cp16(sA_ + a_dst + ((a_seg + j * 16) ^ a_xor), as_ + j * 16); \
    _Pragma("unroll") \
    for (int j = 0; j < 4; j++) \
        cp16(sA_ + b_dst + ((b_seg + j * 16) ^ b_xor), bs_ + j * 16); \
} while (0)

    // ---- fragment addressing ----
    const int wm = UP ? (wid >> 1) : (wid & 1);
    const int wn = UP ? (wid & 1) : (wid >> 1);
    const int m_off = wm * (UP ? 32 : 64);

    uint32_t aoffc[NMI], axorl[NMI];
#pragma unroll
    for (int mi = 0; mi < NMI; mi++) {
        int ar = m_off + mi * 16 + (lane & 15);
        aoffc[mi] = (uint32_t)(ar * 128);
        axorl[mi] = (uint32_t)((ar & 7) << 4);
    }
    const uint32_t akp = (uint32_t)((lane >> 4) * 16);

    const int kr0 = ((lane >> 3) & 1) * 8 + (lane & 7);
    const uint32_t bxorl = (uint32_t)((kr0 & 7) << 4);
    const int noct = (lane >> 4) & 1;
    uint32_t boffc[NBG];
#pragma unroll
    for (int g = 0; g < NBG; g++) {
        int nb = UP ? ((g >= 2 ? 64 : 0) + wn * 32 + (g & 1) * 16)
                    : (wn * 32 + g * 16);
        uint32_t nbyte = (uint32_t)((nb + noct * 8) * 2);
        boffc[g] = 16384u + (uint32_t)(kr0 * 256) + (nbyte ^ bxorl);
    }

    float acc[NMI * NNT][4];
#pragma unroll
    for (int i = 0; i < NMI * NNT; i++)
#pragma unroll
        for (int j = 0; j < 4; j++) acc[i][j] = 0.0f;

    // ---- 3-stage pipeline ----
    ISSUE(0, 0);
    asm volatile("cp.async.commit_group;" ::: "memory");
    ISSUE(1, 1);
    asm volatile("cp.async.commit_group;" ::: "memory");

    for (int it = 0; it < NCH; it++) {
        if (it + 2 < NCH) ISSUE(it + 2, (it + 2) % 3);
        asm volatile("cp.async.commit_group;" ::: "memory");
        asm volatile("cp.async.wait_group 2;" ::: "memory");
        __syncthreads();
        const uint32_t sb = sbase + (uint32_t)(it % 3) * 32768u;
#pragma unroll
        for (int ks = 0; ks < 4; ks++) {
            uint32_t af[NMI][4];
#pragma unroll
            for (int mi = 0; mi < NMI; mi++)
                ldm4(af[mi], sb + aoffc[mi] + (((uint32_t)(ks * 32) + akp) ^ axorl[mi]));
            uint32_t bf[NBG][4];
#pragma unroll
            for (int g = 0; g < NBG; g++)
                ldm4t(bf[g], sb + boffc[g] + (uint32_t)(ks * 4096));
#pragma unroll
            for (int mi = 0; mi < NMI; mi++)
#pragma unroll
                for (int nt = 0; nt < NNT; nt++)
                    mma16(acc[mi * NNT + nt], af[mi],
                          bf[nt >> 1][(nt & 1) * 2], bf[nt >> 1][(nt & 1) * 2 + 1]);
        }
        __syncthreads();
    }
#undef ISSUE

    // ---- epilogue ----
    const int rbase = lane >> 2;
    const int cbase = (lane & 3) * 2;
    if (UP) {
#pragma unroll
        for (int mi = 0; mi < NMI; mi++) {
#pragma unroll
            for (int h = 0; h < 2; h++) {
                const int m = m0 + m_off + mi * 16 + rbase + h * 8;
                if (m >= rows) continue;
#pragma unroll
                for (int nt = 0; nt < 4; nt++) {
                    const int f = n0 + wn * 32 + nt * 8 + cbase;
                    float c1a = acc[mi * NNT + nt][h * 2 + 0] + bias0[(size_t)e * FF + f];
                    float c1b = acc[mi * NNT + nt][h * 2 + 1] + bias0[(size_t)e * FF + f + 1];
                    float c2a = acc[mi * NNT + nt + 4][h * 2 + 0] + bias1[(size_t)e * FF + f];
                    float c2b = acc[mi * NNT + nt + 4][h * 2 + 1] + bias1[(size_t)e * FF + f + 1];
                    __half2 hv = __floats2half2_rn(gelu_exact(c1a) * c2a, gelu_exact(c1b) * c2b);
                    __half* dst = (MODE == 0)
                        ? (g_hh + (size_t)m * DIM + (size_t)e * FF + f)
                        : (g_hh + ((size_t)e * CAP + m) * FF + f);
                    *(__half2*)dst = hv;
                }
            }
        }
    } else {
#pragma unroll
        for (int mi = 0; mi < NMI; mi++) {
#pragma unroll
            for (int h = 0; h < 2; h++) {
                const int m = m0 + m_off + mi * 16 + rbase + h * 8;
                if (m >= rows) continue;
                int tok = 0; float w = 0.0f;
                if (MODE == 3) { tok = g_list[e * CAP + m]; w = g_wt[e * CAP + m]; }
#pragma unroll
                for (int nt = 0; nt < 4; nt++) {
                    const int d = n0 + wn * 32 + nt * 8 + cbase;
                    float v0 = acc[mi * NNT + nt][h * 2 + 0];
                    float v1 = acc[mi * NNT + nt][h * 2 + 1];
                    if (MODE == 2) {
                        size_t o = (size_t)m * DIM + d;
                        float2 xv = *(const float2*)(xres + o);
                        float2 ov = make_float2(
                            xv.x + v0 + bias0[d] + bias0[DIM + d],
                            xv.y + v1 + bias0[d + 1] + bias0[DIM + d + 1]);
                        *(float2*)(outp + o) = ov;
                    } else {
                        float* dst = outp + (size_t)tok * DIM + d;
                        atomicAdd(dst + 0, w * (v0 + bias0[(size_t)e * DIM + d]));
                        atomicAdd(dst + 1, w * (v1 + bias0[(size_t)e * DIM + d + 1]));
                    }
                }
            }
        }
    }
}

// ---------- launch ----------
extern "C" void kernel_launch(void* const* d_in, const int* in_sizes, int n_in,
                              void* d_out, int out_size) {
    const float* x   = (const float*)d_in[0];
    const float* wa  = (const float*)d_in[1];
    const float* rg  = (const float*)d_in[2];
    const float* rgb = (const float*)d_in[3];
    const float* rw1 = (const float*)d_in[4];
    const float* rb1 = (const float*)d_in[5];
    const float* rw2 = (const float*)d_in[6];
    const float* rb2 = (const float*)d_in[7];
    const float* sg  = (const float*)d_in[8];
    const float* sgb = (const float*)d_in[9];
    const float* sw1 = (const float*)d_in[10];
    const float* sb1 = (const float*)d_in[11];
    const float* sw2 = (const float*)d_in[12];
    const float* sb2 = (const float*)d_in[13];
    float* out = (float*)d_out;

    const int smem = 3 * 32768;
    cudaFuncSetAttribute(mma_kernel<0>, cudaFuncAttributeMaxDynamicSharedMemorySize, smem);
    cudaFuncSetAttribute(mma_kernel<1>, cudaFuncAttributeMaxDynamicSharedMemorySize, smem);
    cudaFuncSetAttribute(mma_kernel<2>, cudaFuncAttributeMaxDynamicSharedMemorySize, smem);
    cudaFuncSetAttribute(mma_kernel<3>, cudaFuncAttributeMaxDynamicSharedMemorySize, smem);

    // fp32 -> fp16 conversions
    auto cvt = [&](const float* s, size_t off, size_t n) {
        cvt_kernel<<<(unsigned)(n / 1024), 256>>>(s, off, n);
    };
    cvt(x,   OXH,  (size_t)N_TOK * DIM);
    cvt(rg,  ORG,  (size_t)NE * DIM * FF);
    cvt(rw1, ORW1, (size_t)NE * DIM * FF);
    cvt(rw2, ORW2, (size_t)NE * FF * DIM);
    cvt(sg,  OSG,  (size_t)2 * DIM * FF);
    cvt(sw1, OSW1, (size_t)2 * DIM * FF);
    cvt(sw2, OSW2, (size_t)2 * FF * DIM);

    zero_cnt_kernel<<<1, 32>>>();
    router_kernel<<<N_TOK / 4, 128>>>(x, wa);

    // shared: up (dual-B), down (+x +biases) — down must precede routed-up (g_hh reuse)
    mma_kernel<0><<<dim3(N_TOK / 128, FF / 64, 2), 256, smem>>>(sgb, sb1, nullptr, nullptr);
    mma_kernel<2><<<dim3(N_TOK / 128, DIM / 128, 1), 256, smem>>>(sb2, nullptr, x, out);

    // routed: up (gathered rows), weighted scatter-add down
    mma_kernel<1><<<dim3(CAP / 128, FF / 64, NE), 256, smem>>>(rgb, rb1, nullptr, nullptr);
    mma_kernel<3><<<dim3(CAP / 128, DIM / 128, NE), 256, smem>>>(rb2, nullptr, nullptr, out);
}

// round 6
// speedup vs baseline: 5.3313x; 1.1834x over previous
#include <cuda_runtime.h>
#include <cuda_fp16.h>
#include <cstdint>
#include <math.h>

#define N_TOK 4096
#define DIM   2048
#define FF    1024
#define NE    16
#define CAP   4096

// half-buffer offsets (in halves)
#define OXH  0ull
#define ORG  (8ull  << 20)
#define ORW1 (40ull << 20)
#define ORW2 (72ull << 20)
#define OSG  (104ull << 20)
#define OSW1 (108ull << 20)
#define OSW2 (112ull << 20)

__device__ int    g_cnt[NE];
__device__ int    g_list[NE * CAP];
__device__ float  g_wt[NE * CAP];
__device__ __half g_half[116ull << 20];
__device__ __half g_hh[(size_t)NE * CAP * FF];

// ---------- helpers ----------
__device__ __forceinline__ uint32_t smem_u32(const void* p) {
    uint32_t a;
    asm("{ .reg .u64 t; cvta.to.shared.u64 t, %1; cvt.u32.u64 %0, t; }" : "=r"(a) : "l"(p));
    return a;
}
__device__ __forceinline__ void cp16(uint32_t dst, const void* src) {
    asm volatile("cp.async.cg.shared.global [%0], [%1], 16;" :: "r"(dst), "l"(src));
}
__device__ __forceinline__ void ldm4(uint32_t* r, uint32_t a) {
    asm volatile("ldmatrix.sync.aligned.m8n8.x4.shared.b16 {%0,%1,%2,%3}, [%4];"
                 : "=r"(r[0]), "=r"(r[1]), "=r"(r[2]), "=r"(r[3]) : "r"(a));
}
__device__ __forceinline__ void ldm4t(uint32_t* r, uint32_t a) {
    asm volatile("ldmatrix.sync.aligned.m8n8.x4.trans.shared.b16 {%0,%1,%2,%3}, [%4];"
                 : "=r"(r[0]), "=r"(r[1]), "=r"(r[2]), "=r"(r[3]) : "r"(a));
}
__device__ __forceinline__ void mma16(float* d, const uint32_t* a, uint32_t b0, uint32_t b1) {
    asm volatile("mma.sync.aligned.m16n8k16.row.col.f32.f16.f16.f32 "
                 "{%0,%1,%2,%3},{%4,%5,%6,%7},{%8,%9},{%0,%1,%2,%3};"
                 : "+f"(d[0]), "+f"(d[1]), "+f"(d[2]), "+f"(d[3])
                 : "r"(a[0]), "r"(a[1]), "r"(a[2]), "r"(a[3]), "r"(b0), "r"(b1));
}
__device__ __forceinline__ float gelu_exact(float v) {
    return 0.5f * v * (1.0f + erff(v * 0.70710678118654752440f));
}

// ---------- conversion fp32 -> fp16 ----------
__global__ void cvt_kernel(const float* __restrict__ src, size_t dofs, size_t n) {
    size_t i = ((size_t)blockIdx.x * 256 + threadIdx.x) * 4;
    if (i >= n) return;
    float4 v = *(const float4*)(src + i);
    __half2* d = (__half2*)(g_half + dofs + i);
    d[0] = __floats2half2_rn(v.x, v.y);
    d[1] = __floats2half2_rn(v.z, v.w);
}

// ---------- router ----------
__global__ void zero_cnt_kernel() { if (threadIdx.x < NE) g_cnt[threadIdx.x] = 0; }

__global__ void router_kernel(const float* __restrict__ x, const float* __restrict__ wa) {
    int t = (blockIdx.x * blockDim.x + threadIdx.x) >> 5;
    int lane = threadIdx.x & 31;
    if (t >= N_TOK) return;
    float acc[NE];
#pragma unroll
    for (int e = 0; e < NE; e++) acc[e] = 0.0f;
    const float* xr = x + (size_t)t * DIM;
    for (int d = lane; d < DIM; d += 32) {
        float xv = xr[d];
#pragma unroll
        for (int e = 0; e < NE; e++) acc[e] += xv * wa[(size_t)d * NE + e];
    }
#pragma unroll
    for (int e = 0; e < NE; e++)
#pragma unroll
        for (int o = 16; o > 0; o >>= 1) acc[e] += __shfl_xor_sync(0xffffffffu, acc[e], o);
    if (lane == 0) {
        float aff[NE];
#pragma unroll
        for (int e = 0; e < NE; e++) aff[e] = 1.0f / (1.0f + expf(-acc[e]));
        int e1 = 0; float p1 = aff[0];
#pragma unroll
        for (int e = 1; e < NE; e++) if (aff[e] > p1) { p1 = aff[e]; e1 = e; }
        int e2 = (e1 == 0) ? 1 : 0; float p2 = aff[e2];
#pragma unroll
        for (int e = 0; e < NE; e++) if (e != e1 && aff[e] > p2) { p2 = aff[e]; e2 = e; }
        float inv = 1.0f / (p1 + p2);
        int q1 = atomicAdd(&g_cnt[e1], 1);
        g_list[e1 * CAP + q1] = t; g_wt[e1 * CAP + q1] = p1 * inv;
        int q2 = atomicAdd(&g_cnt[e2], 1);
        g_list[e2 * CAP + q2] = t; g_wt[e2 * CAP + q2] = p2 * inv;
    }
}

// ---------- fp16 warp-MMA GEMM: 128x128 CTA, 4 warps of 64x64, 3-stage cp.async ----------
// modes: 0 up-shared, 1 up-routed, 2 down-shared, 3 down-routed
template <int MODE>
__global__ void __launch_bounds__(128, 2) mma_kernel(
    const float* __restrict__ bias0, const float* __restrict__ bias1,
    const float* __restrict__ xres, float* __restrict__ outp)
{
    constexpr bool UP = (MODE <= 1);
    constexpr int KT  = (MODE == 3) ? FF : DIM;
    constexpr int LDA = (MODE == 3) ? FF : DIM;
    constexpr int LDB = UP ? FF : DIM;
    constexpr int NCH = KT / 64;

    const int e = blockIdx.z;
    const int rows = (MODE == 1 || MODE == 3) ? g_cnt[e] : N_TOK;
    const int m0 = blockIdx.x * 128;
    if (m0 >= rows) return;
    const int n0f = blockIdx.y * (UP ? 64 : 128);

    extern __shared__ char dynsm[];
    __shared__ int s_row[128];
    const int tid = threadIdx.x, wid = tid >> 5, lane = tid & 31;
    const uint32_t sbase = smem_u32(dynsm);

    {
        int mm = m0 + tid;
        s_row[tid] = (MODE == 1) ? g_list[e * CAP + (mm < rows ? mm : m0)] : mm;
    }
    __syncthreads();

    // ---- loader setup (128 threads) ----
    const __half* Ah = UP ? (g_half + OXH)
                          : (MODE == 2 ? g_hh : g_hh + (size_t)e * CAP * FF);
    int rix[8];
#pragma unroll
    for (int i = 0; i < 8; i++) rix[i] = s_row[(tid >> 3) + i * 16];

    const int c = tid & 15;
    const __half* Bb;
    if (UP) {
        const __half* G = g_half + (MODE == 0 ? OSG : ORG) + (size_t)e * DIM * FF;
        const __half* W = g_half + (MODE == 0 ? OSW1 : ORW1) + (size_t)e * DIM * FF;
        int f = n0f + (c >> 2) * 16 + (c & 1) * 8;
        Bb = (((c >> 1) & 1) ? W : G) + f;
    } else {
        Bb = g_half + (MODE == 2 ? OSW2 : (ORW2 + (size_t)e * FF * DIM)) + n0f + c * 8;
    }
    const int akseg = tid & 7, arow = tid >> 3, kroww = tid >> 4;
    const uint32_t a_dst = (uint32_t)(arow * 128 + ((akseg * 16) ^ ((arow & 7) << 4)));
    const uint32_t b_dst = (uint32_t)(16384 + kroww * 256 + ((c * 16) ^ (kroww << 4)));

#define ISSUE(k0g, buf) do { \
    uint32_t sB_ = sbase + (uint32_t)(buf) * 32768u; \
    _Pragma("unroll") \
    for (int i_ = 0; i_ < 8; i_++) { \
        cp16(sB_ + a_dst + (uint32_t)i_ * 2048u, \
             Ah + (size_t)rix[i_] * LDA + (k0g) + akseg * 8); \
        cp16(sB_ + b_dst + (uint32_t)i_ * 2048u, \
             Bb + (size_t)((k0g) + kroww + i_ * 8) * LDB); \
    } \
} while (0)
#define COMMIT() asm volatile("cp.async.commit_group;" ::: "memory")

    // ---- fragment addressing: warp (wm, wn), 64x64 tile ----
    const int wm = wid & 1, wn = wid >> 1;
    const int m_off = wm * 64;
    uint32_t aoffc[4], axorl[4];
#pragma unroll
    for (int mi = 0; mi < 4; mi++) {
        int ar = m_off + mi * 16 + (lane & 15);
        aoffc[mi] = (uint32_t)(ar * 128);
        axorl[mi] = (uint32_t)((ar & 7) << 4);
    }
    const uint32_t akp = (uint32_t)((lane >> 4) * 16);
    const int kr0 = ((lane >> 3) & 1) * 8 + (lane & 7);
    const int noct = (lane >> 4) & 1;
    uint32_t boffc[4];
#pragma unroll
    for (int g = 0; g < 4; g++) {
        int nb = wn * 64 + g * 16;
        uint32_t nbyte = (uint32_t)((nb + noct * 8) * 2);
        boffc[g] = 16384u + (uint32_t)(kr0 * 256) + (nbyte ^ (uint32_t)((kr0 & 7) << 4));
    }

    float acc[32][4];
#pragma unroll
    for (int i = 0; i < 32; i++)
#pragma unroll
        for (int j = 0; j < 4; j++) acc[i][j] = 0.0f;

    // ---- 3-stage pipeline, one sync per chunk ----
    ISSUE(0, 0);  COMMIT();
    ISSUE(64, 1); COMMIT();

    for (int it = 0; it < NCH; it++) {
        asm volatile("cp.async.wait_group 1;" ::: "memory");
        __syncthreads();
        if (it + 2 < NCH) ISSUE((it + 2) * 64, (it + 2) % 3);
        COMMIT();
        const uint32_t sb = sbase + (uint32_t)(it % 3) * 32768u;
#pragma unroll
        for (int ks = 0; ks < 4; ks++) {
            uint32_t af[4][4];
#pragma unroll
            for (int mi = 0; mi < 4; mi++)
                ldm4(af[mi], sb + aoffc[mi] + (((uint32_t)(ks * 32) + akp) ^ axorl[mi]));
            uint32_t bf[4][4];
#pragma unroll
            for (int g = 0; g < 4; g++)
                ldm4t(bf[g], sb + boffc[g] + (uint32_t)(ks * 4096));
#pragma unroll
            for (int mi = 0; mi < 4; mi++)
#pragma unroll
                for (int nt = 0; nt < 8; nt++)
                    mma16(acc[mi * 8 + nt], af[mi],
                          bf[nt >> 1][(nt & 1) * 2], bf[nt >> 1][(nt & 1) * 2 + 1]);
        }
    }
#undef ISSUE
#undef COMMIT

    // ---- epilogue ----
    const int rbase = lane >> 2;
    const int cbase = (lane & 3) * 2;
    if (UP) {
#pragma unroll
        for (int mi = 0; mi < 4; mi++) {
#pragma unroll
            for (int h = 0; h < 2; h++) {
                const int m = m0 + m_off + mi * 16 + rbase + h * 8;
                if (m >= rows) continue;
#pragma unroll
                for (int gi = 0; gi < 4; gi++) {
                    const int g = (gi & 1) + (gi >> 1) * 4;  // 0,1,4,5
                    const int f = n0f + wn * 32 + (g >> 2) * 16 + (g & 1) * 8 + cbase;
                    float c1a = acc[mi * 8 + g][h * 2 + 0] + bias0[(size_t)e * FF + f];
                    float c1b = acc[mi * 8 + g][h * 2 + 1] + bias0[(size_t)e * FF + f + 1];
                    float c2a = acc[mi * 8 + g + 2][h * 2 + 0] + bias1[(size_t)e * FF + f];
                    float c2b = acc[mi * 8 + g + 2][h * 2 + 1] + bias1[(size_t)e * FF + f + 1];
                    __half2 hv = __floats2half2_rn(gelu_exact(c1a) * c2a, gelu_exact(c1b) * c2b);
                    __half* dst = (MODE == 0)
                        ? (g_hh + (size_t)m * DIM + (size_t)e * FF + f)
                        : (g_hh + ((size_t)e * CAP + m) * FF + f);
                    *(__half2*)dst = hv;
                }
            }
        }
    } else {
#pragma unroll
        for (int mi = 0; mi < 4; mi++) {
#pragma unroll
            for (int h = 0; h < 2; h++) {
                const int m = m0 + m_off + mi * 16 + rbase + h * 8;
                if (m >= rows) continue;
                int tok = 0; float w = 0.0f;
                if (MODE == 3) { tok = g_list[e * CAP + m]; w = g_wt[e * CAP + m]; }
#pragma unroll
                for (int nt = 0; nt < 8; nt++) {
                    const int d = n0f + wn * 64 + nt * 8 + cbase;
                    float v0 = acc[mi * 8 + nt][h * 2 + 0];
                    float v1 = acc[mi * 8 + nt][h * 2 + 1];
                    if (MODE == 2) {
                        size_t o = (size_t)m * DIM + d;
                        float2 xv = *(const float2*)(xres + o);
                        float2 ov = make_float2(
                            xv.x + v0 + bias0[d] + bias0[DIM + d],
                            xv.y + v1 + bias0[d + 1] + bias0[DIM + d + 1]);
                        *(float2*)(outp + o) = ov;
                    } else {
                        float* dst = outp + (size_t)tok * DIM + d;
                        atomicAdd(dst + 0, w * (v0 + bias0[(size_t)e * DIM + d]));
                        atomicAdd(dst + 1, w * (v1 + bias0[(size_t)e * DIM + d + 1]));
                    }
                }
            }
        }
    }
}

// ---------- launch ----------
extern "C" void kernel_launch(void* const* d_in, const int* in_sizes, int n_in,
                              void* d_out, int out_size) {
    const float* x   = (const float*)d_in[0];
    const float* wa  = (const float*)d_in[1];
    const float* rg  = (const float*)d_in[2];
    const float* rgb = (const float*)d_in[3];
    const float* rw1 = (const float*)d_in[4];
    const float* rb1 = (const float*)d_in[5];
    const float* rw2 = (const float*)d_in[6];
    const float* rb2 = (const float*)d_in[7];
    const float* sg  = (const float*)d_in[8];
    const float* sgb = (const float*)d_in[9];
    const float* sw1 = (const float*)d_in[10];
    const float* sb1 = (const float*)d_in[11];
    const float* sw2 = (const float*)d_in[12];
    const float* sb2 = (const float*)d_in[13];
    float* out = (float*)d_out;

    const int smem = 3 * 32768;
    cudaFuncSetAttribute(mma_kernel<0>, cudaFuncAttributeMaxDynamicSharedMemorySize, smem);
    cudaFuncSetAttribute(mma_kernel<1>, cudaFuncAttributeMaxDynamicSharedMemorySize, smem);
    cudaFuncSetAttribute(mma_kernel<2>, cudaFuncAttributeMaxDynamicSharedMemorySize, smem);
    cudaFuncSetAttribute(mma_kernel<3>, cudaFuncAttributeMaxDynamicSharedMemorySize, smem);

    auto cvt = [&](const float* s, size_t off, size_t n) {
        cvt_kernel<<<(unsigned)(n / 1024), 256>>>(s, off, n);
    };
    cvt(x,   OXH,  (size_t)N_TOK * DIM);
    cvt(rg,  ORG,  (size_t)NE * DIM * FF);
    cvt(rw1, ORW1, (size_t)NE * DIM * FF);
    cvt(rw2, ORW2, (size_t)NE * FF * DIM);
    cvt(sg,  OSG,  (size_t)2 * DIM * FF);
    cvt(sw1, OSW1, (size_t)2 * DIM * FF);
    cvt(sw2, OSW2, (size_t)2 * FF * DIM);

    zero_cnt_kernel<<<1, 32>>>();
    router_kernel<<<N_TOK / 4, 128>>>(x, wa);

    // shared: up (dual-B interleaved), down (+x +biases) — down precedes routed-up (g_hh reuse)
    mma_kernel<0><<<dim3(N_TOK / 128, FF / 64, 2), 128, smem>>>(sgb, sb1, nullptr, nullptr);
    mma_kernel<2><<<dim3(N_TOK / 128, DIM / 128, 1), 128, smem>>>(sb2, nullptr, x, out);

    // routed: up (gathered rows), weighted scatter-add down
    mma_kernel<1><<<dim3(CAP / 128, FF / 64, NE), 128, smem>>>(rgb, rb1, nullptr, nullptr);
    mma_kernel<3><<<dim3(CAP / 128, DIM / 128, NE), 128, smem>>>(rb2, nullptr, nullptr, out);
}